// round 1
// baseline (speedup 1.0000x reference)
#include <cuda_runtime.h>
#include <math.h>

#define S_TOK 1024
#define CDIM  512
#define NTOK  16384   // B * S_TOK

// ---- scratch (static device globals; no runtime allocation) ----
__device__ float g_xn  [NTOK * CDIM];
__device__ float g_q   [NTOK * CDIM];
__device__ float g_k   [NTOK * CDIM];
__device__ float g_v   [NTOK * CDIM];
__device__ float g_attn[NTOK * CDIM];

// ============================================================
// GroupNorm: one block per (b, group). 32 groups of 16 channels.
// ============================================================
__global__ void gn_kernel(const float* __restrict__ x,
                          const float* __restrict__ gamma,
                          const float* __restrict__ beta,
                          float* __restrict__ xn) {
    int bg = blockIdx.x;            // b*32 + g
    int b = bg >> 5, g = bg & 31;
    const float* xb  = x  + (size_t)b * S_TOK * CDIM + g * 16;
    float*       xnb = xn + (size_t)b * S_TOK * CDIM + g * 16;

    float sum = 0.f, sumsq = 0.f;
    for (int t = threadIdx.x; t < 16384; t += 256) {
        int s = t >> 4, c = t & 15;
        float v = xb[s * CDIM + c];
        sum += v; sumsq += v * v;
    }
    __shared__ float red[256], red2[256];
    red[threadIdx.x] = sum; red2[threadIdx.x] = sumsq;
    __syncthreads();
    for (int off = 128; off > 0; off >>= 1) {
        if (threadIdx.x < off) {
            red[threadIdx.x]  += red[threadIdx.x + off];
            red2[threadIdx.x] += red2[threadIdx.x + off];
        }
        __syncthreads();
    }
    float mean = red[0] * (1.f / 16384.f);
    float var  = red2[0] * (1.f / 16384.f) - mean * mean;
    float inv  = rsqrtf(var + 1e-5f);

    for (int t = threadIdx.x; t < 16384; t += 256) {
        int s = t >> 4, c = t & 15;
        float v = xb[s * CDIM + c];
        xnb[s * CDIM + c] = (v - mean) * inv * gamma[g * 16 + c] + beta[g * 16 + c];
    }
}

// ============================================================
// Tiled SGEMM: C[M=16384, N=512] (+)= Ashift[M,512] @ W[512,N]
// BM=128, BN=128, BK=8, 256 threads, 8x8 microtile.
// dh/dw: spatial shift for conv taps (rows outside image -> 0).
// epilogue: += bias[n] + residual[m,n]
// ============================================================
#define BM 128
#define BN 128
#define BK 8
#define APAD 4   // smem row stride = 132

__global__ __launch_bounds__(256)
void gemm_kernel(const float* __restrict__ A, const float* __restrict__ W,
                 float* __restrict__ C, int dh, int dw, int accumulate,
                 const float* __restrict__ bias,
                 const float* __restrict__ residual, int epilogue) {
    __shared__ float As[BK][BM + APAD];
    __shared__ float Ws[BK][BN + APAD];

    int tid = threadIdx.x;
    int m0 = blockIdx.y * BM, n0 = blockIdx.x * BN;

    // A-tile loader mapping: each thread loads one float4 (row, 4 k's)
    int arow = tid >> 1;             // 0..127
    int akq  = (tid & 1) * 4;        // k offset 0 or 4
    int mg = m0 + arow;
    int b = mg >> 10, s = mg & 1023, h = s >> 5, w = s & 31;
    int hh = h + dh, ww = w + dw;
    bool avalid = ((unsigned)hh < 32u) && ((unsigned)ww < 32u);
    const float* aptr = A + ((size_t)((b << 10) + (hh << 5) + ww)) * CDIM + akq;

    // W-tile loader: one float4 per thread
    int wk = tid >> 5;               // 0..7
    int wn = (tid & 31) * 4;         // 0..124
    const float* wptr = W + (size_t)wk * CDIM + n0 + wn;

    int ty = tid >> 4, tx = tid & 15;
    float acc[8][8];
#pragma unroll
    for (int i = 0; i < 8; i++)
#pragma unroll
        for (int j = 0; j < 8; j++) acc[i][j] = 0.f;

    for (int k0 = 0; k0 < CDIM; k0 += BK) {
        float4 av = avalid ? *(const float4*)(aptr + k0) : make_float4(0.f, 0.f, 0.f, 0.f);
        float4 wv = *(const float4*)(wptr + (size_t)k0 * CDIM);
        __syncthreads();
        As[akq + 0][arow] = av.x;
        As[akq + 1][arow] = av.y;
        As[akq + 2][arow] = av.z;
        As[akq + 3][arow] = av.w;
        *(float4*)&Ws[wk][wn] = wv;
        __syncthreads();
#pragma unroll
        for (int k = 0; k < BK; k++) {
            float4 a0 = *(const float4*)&As[k][ty * 8];
            float4 a1 = *(const float4*)&As[k][ty * 8 + 4];
            float4 b0 = *(const float4*)&Ws[k][tx * 8];
            float4 b1 = *(const float4*)&Ws[k][tx * 8 + 4];
            float ar[8] = {a0.x, a0.y, a0.z, a0.w, a1.x, a1.y, a1.z, a1.w};
            float br[8] = {b0.x, b0.y, b0.z, b0.w, b1.x, b1.y, b1.z, b1.w};
#pragma unroll
            for (int i = 0; i < 8; i++)
#pragma unroll
                for (int j = 0; j < 8; j++) acc[i][j] += ar[i] * br[j];
        }
    }

#pragma unroll
    for (int i = 0; i < 8; i++) {
        int m = m0 + ty * 8 + i;
        float* crow = C + (size_t)m * CDIM + n0 + tx * 8;
#pragma unroll
        for (int jq = 0; jq < 2; jq++) {
            float4 v = make_float4(acc[i][jq * 4], acc[i][jq * 4 + 1],
                                   acc[i][jq * 4 + 2], acc[i][jq * 4 + 3]);
            if (accumulate) {
                float4 p = *(float4*)(crow + jq * 4);
                v.x += p.x; v.y += p.y; v.z += p.z; v.w += p.w;
            }
            if (epilogue) {
                int n = n0 + tx * 8 + jq * 4;
                const float* r = residual + (size_t)m * CDIM + n;
                v.x += bias[n + 0] + r[0];
                v.y += bias[n + 1] + r[1];
                v.z += bias[n + 2] + r[2];
                v.w += bias[n + 3] + r[3];
            }
            *(float4*)(crow + jq * 4) = v;
        }
    }
}

// ============================================================
// Flash attention: grid (16 qtiles, 8 heads, 16 batch), 256 thr.
// 64x64 tiles, 4x4 fragments, online softmax (fp32).
// q/k/v layout: [b, s, head, d] row-major with row stride 512.
// ============================================================
#define KPAD 68   // 64 + 4, multiple of 4 for float4 alignment

__global__ __launch_bounds__(256)
void attn_kernel(const float* __restrict__ q, const float* __restrict__ k,
                 const float* __restrict__ v, float* __restrict__ o) {
    extern __shared__ float sm[];
    float* Qs = sm;
    float* Ks = Qs + 64 * KPAD;
    float* Vs = Ks + 64 * KPAD;
    float* Ps = Vs + 64 * KPAD;

    int qt = blockIdx.x, head = blockIdx.y, b = blockIdx.z;
    int tid = threadIdx.x;
    int ty = tid >> 4, tx = tid & 15;

    size_t base = ((size_t)b * S_TOK) * CDIM + head * 64;
    const float* qb = q + base;
    const float* kb = k + base;
    const float* vb = v + base;

    // load Q tile (64 x 64)
#pragma unroll
    for (int i = 0; i < 4; i++) {
        int idx = tid + i * 256;
        int row = idx >> 4, qq = (idx & 15) * 4;
        *(float4*)&Qs[row * KPAD + qq] =
            *(const float4*)(qb + (size_t)(qt * 64 + row) * CDIM + qq);
    }

    float o_acc[4][4];
    float mi[4], li[4];
#pragma unroll
    for (int i = 0; i < 4; i++) {
        mi[i] = -1e30f; li[i] = 0.f;
#pragma unroll
        for (int j = 0; j < 4; j++) o_acc[i][j] = 0.f;
    }

    for (int kt = 0; kt < 16; kt++) {
        __syncthreads();
#pragma unroll
        for (int i = 0; i < 4; i++) {
            int idx = tid + i * 256;
            int row = idx >> 4, qq = (idx & 15) * 4;
            *(float4*)&Ks[row * KPAD + qq] =
                *(const float4*)(kb + (size_t)(kt * 64 + row) * CDIM + qq);
            *(float4*)&Vs[row * KPAD + qq] =
                *(const float4*)(vb + (size_t)(kt * 64 + row) * CDIM + qq);
        }
        __syncthreads();

        // S = Q @ K^T  (64x64 tile, 4x4 per thread)
        float sv[4][4];
#pragma unroll
        for (int i = 0; i < 4; i++)
#pragma unroll
            for (int j = 0; j < 4; j++) sv[i][j] = 0.f;

        for (int d = 0; d < 64; d += 4) {
            float4 a[4], bb[4];
#pragma unroll
            for (int i = 0; i < 4; i++) a[i] = *(const float4*)&Qs[(ty * 4 + i) * KPAD + d];
#pragma unroll
            for (int j = 0; j < 4; j++) bb[j] = *(const float4*)&Ks[(tx * 4 + j) * KPAD + d];
#pragma unroll
            for (int i = 0; i < 4; i++)
#pragma unroll
                for (int j = 0; j < 4; j++)
                    sv[i][j] += a[i].x * bb[j].x + a[i].y * bb[j].y +
                                a[i].z * bb[j].z + a[i].w * bb[j].w;
        }

        // online softmax (row stats shared across 16 tx lanes via shuffles)
#pragma unroll
        for (int i = 0; i < 4; i++) {
            float tmax = -1e30f;
#pragma unroll
            for (int j = 0; j < 4; j++) {
                sv[i][j] *= 0.125f;           // 1/sqrt(64)
                tmax = fmaxf(tmax, sv[i][j]);
            }
#pragma unroll
            for (int off = 8; off >= 1; off >>= 1)
                tmax = fmaxf(tmax, __shfl_xor_sync(0xffffffffu, tmax, off));
            float newm = fmaxf(mi[i], tmax);
            float c = __expf(mi[i] - newm);
            float rs = 0.f;
#pragma unroll
            for (int j = 0; j < 4; j++) {
                sv[i][j] = __expf(sv[i][j] - newm);
                rs += sv[i][j];
            }
#pragma unroll
            for (int off = 8; off >= 1; off >>= 1)
                rs += __shfl_xor_sync(0xffffffffu, rs, off);
            li[i] = li[i] * c + rs;
            mi[i] = newm;
#pragma unroll
            for (int j = 0; j < 4; j++) o_acc[i][j] *= c;
#pragma unroll
            for (int j = 0; j < 4; j++)
                Ps[(ty * 4 + i) * KPAD + tx * 4 + j] = sv[i][j];
        }
        __syncthreads();

        // O += P @ V
        for (int kk = 0; kk < 64; kk += 4) {
            float4 p[4];
#pragma unroll
            for (int i = 0; i < 4; i++) p[i] = *(const float4*)&Ps[(ty * 4 + i) * KPAD + kk];
            float4 v0 = *(const float4*)&Vs[(kk + 0) * KPAD + tx * 4];
            float4 v1 = *(const float4*)&Vs[(kk + 1) * KPAD + tx * 4];
            float4 v2 = *(const float4*)&Vs[(kk + 2) * KPAD + tx * 4];
            float4 v3 = *(const float4*)&Vs[(kk + 3) * KPAD + tx * 4];
#pragma unroll
            for (int i = 0; i < 4; i++) {
                o_acc[i][0] += p[i].x * v0.x + p[i].y * v1.x + p[i].z * v2.x + p[i].w * v3.x;
                o_acc[i][1] += p[i].x * v0.y + p[i].y * v1.y + p[i].z * v2.y + p[i].w * v3.y;
                o_acc[i][2] += p[i].x * v0.z + p[i].y * v1.z + p[i].z * v2.z + p[i].w * v3.z;
                o_acc[i][3] += p[i].x * v0.w + p[i].y * v1.w + p[i].z * v2.w + p[i].w * v3.w;
            }
        }
    }

    // normalize and write out (layout [b, s, head, d])
#pragma unroll
    for (int i = 0; i < 4; i++) {
        float inv = 1.f / li[i];
        int srow = qt * 64 + ty * 4 + i;
        float* orow = o + ((size_t)b * S_TOK + srow) * CDIM + head * 64 + tx * 4;
        float4 val = make_float4(o_acc[i][0] * inv, o_acc[i][1] * inv,
                                 o_acc[i][2] * inv, o_acc[i][3] * inv);
        *(float4*)orow = val;
    }
}

// ============================================================
// launch
// ============================================================
extern "C" void kernel_launch(void* const* d_in, const int* in_sizes, int n_in,
                              void* d_out, int out_size) {
    const float* x       = (const float*)d_in[0];
    const float* gamma   = (const float*)d_in[1];
    const float* beta    = (const float*)d_in[2];
    const float* wq      = (const float*)d_in[3];
    const float* wk      = (const float*)d_in[4];
    const float* wv      = (const float*)d_in[5];
    const float* conv_w  = (const float*)d_in[6];
    const float* conv_b  = (const float*)d_in[7];
    float* out = (float*)d_out;

    float *xn, *qb, *kb, *vb, *ab;
    cudaGetSymbolAddress((void**)&xn, g_xn);
    cudaGetSymbolAddress((void**)&qb, g_q);
    cudaGetSymbolAddress((void**)&kb, g_k);
    cudaGetSymbolAddress((void**)&vb, g_v);
    cudaGetSymbolAddress((void**)&ab, g_attn);

    // GroupNorm
    gn_kernel<<<512, 256>>>(x, gamma, beta, xn);

    // QKV projections
    dim3 ggrid(CDIM / BN, NTOK / BM);
    gemm_kernel<<<ggrid, 256>>>(xn, wq, qb, 0, 0, 0, nullptr, nullptr, 0);
    gemm_kernel<<<ggrid, 256>>>(xn, wk, kb, 0, 0, 0, nullptr, nullptr, 0);
    gemm_kernel<<<ggrid, 256>>>(xn, wv, vb, 0, 0, 0, nullptr, nullptr, 0);

    // Attention
    static int attr_set = 0;
    (void)attr_set;
    cudaFuncSetAttribute(attn_kernel, cudaFuncAttributeMaxDynamicSharedMemorySize,
                         4 * 64 * KPAD * (int)sizeof(float));
    attn_kernel<<<dim3(16, 8, 16), 256, 4 * 64 * KPAD * sizeof(float)>>>(qb, kb, vb, ab);

    // 3x3 conv as 9 shifted accumulating GEMMs; last tap fuses bias + residual
    for (int tap = 0; tap < 9; tap++) {
        int kh = tap / 3, kw = tap % 3;
        const float* wt = conv_w + (size_t)tap * CDIM * CDIM;
        int acc = (tap != 0);
        int epi = (tap == 8);
        gemm_kernel<<<ggrid, 256>>>(ab, wt, out, kh - 1, kw - 1, acc,
                                    epi ? conv_b : nullptr, epi ? x : nullptr, epi);
    }
}

// round 2
// speedup vs baseline: 1.0006x; 1.0006x over previous
#include <cuda_runtime.h>
#include <math.h>

#define S_TOK 1024
#define CDIM  512
#define NTOK  16384   // B * S_TOK

// ---- scratch (static device globals; no runtime allocation) ----
__device__ float g_xn  [NTOK * CDIM];
__device__ float g_q   [NTOK * CDIM];
__device__ float g_k   [NTOK * CDIM];
__device__ float g_v   [NTOK * CDIM];
__device__ float g_attn[NTOK * CDIM];

// ============================================================
// GroupNorm: one block per (b, group). 32 groups of 16 channels.
// ============================================================
__global__ void gn_kernel(const float* __restrict__ x,
                          const float* __restrict__ gamma,
                          const float* __restrict__ beta,
                          float* __restrict__ xn) {
    int bg = blockIdx.x;            // b*32 + g
    int b = bg >> 5, g = bg & 31;
    const float* xb  = x  + (size_t)b * S_TOK * CDIM + g * 16;
    float*       xnb = xn + (size_t)b * S_TOK * CDIM + g * 16;

    float sum = 0.f, sumsq = 0.f;
    for (int t = threadIdx.x; t < 16384; t += 256) {
        int s = t >> 4, c = t & 15;
        float v = xb[s * CDIM + c];
        sum += v; sumsq += v * v;
    }
    __shared__ float red[256], red2[256];
    red[threadIdx.x] = sum; red2[threadIdx.x] = sumsq;
    __syncthreads();
    for (int off = 128; off > 0; off >>= 1) {
        if (threadIdx.x < off) {
            red[threadIdx.x]  += red[threadIdx.x + off];
            red2[threadIdx.x] += red2[threadIdx.x + off];
        }
        __syncthreads();
    }
    float mean = red[0] * (1.f / 16384.f);
    float var  = red2[0] * (1.f / 16384.f) - mean * mean;
    float inv  = rsqrtf(var + 1e-5f);

    for (int t = threadIdx.x; t < 16384; t += 256) {
        int s = t >> 4, c = t & 15;
        float v = xb[s * CDIM + c];
        xnb[s * CDIM + c] = (v - mean) * inv * gamma[g * 16 + c] + beta[g * 16 + c];
    }
}

// ============================================================
// TF32 tensor-core GEMM:
//   C[M=16384, N=512] = sum_{tap} Ashift_tap[M,512] @ W_tap[512,N]
// ntaps=1 -> plain GEMM (QKV). ntaps=9 -> fused 3x3 conv, with
// bias + residual epilogue. 128x128x16 tiles, 8 warps (64x32 each),
// mma.sync.m16n8k8.tf32, double-buffered smem.
// ============================================================
#define ASTR 20    // A smem row stride (words): frag LDS conflict-free
#define BSTR 136   // B smem row stride (words): frag LDS conflict-free

__device__ __forceinline__ unsigned f2tf(float x) {
    unsigned r;
    asm("cvt.rna.tf32.f32 %0, %1;" : "=r"(r) : "f"(x));
    return r;
}

#define MMA_TF32(d, a0, a1, a2, a3, b0, b1)                                 \
    asm volatile(                                                           \
        "mma.sync.aligned.m16n8k8.row.col.f32.tf32.tf32.f32 "               \
        "{%0,%1,%2,%3}, {%4,%5,%6,%7}, {%8,%9}, {%0,%1,%2,%3};\n"           \
        : "+f"(d[0]), "+f"(d[1]), "+f"(d[2]), "+f"(d[3])                    \
        : "r"(a0), "r"(a1), "r"(a2), "r"(a3), "r"(b0), "r"(b1))

__global__ __launch_bounds__(256)
void gemm_tf32(const float* __restrict__ A, const float* __restrict__ W0,
               float* __restrict__ C, int ntaps,
               const float* __restrict__ bias,
               const float* __restrict__ residual, int epi) {
    __shared__ unsigned As[2][128 * ASTR];
    __shared__ unsigned Bs[2][16 * BSTR];

    int tid = threadIdx.x;
    int warp = tid >> 5, lane = tid & 31;
    int g = lane >> 2, t = lane & 3;
    int m0 = blockIdx.y * 128, n0 = blockIdx.x * 128;
    int wm = (warp >> 2) * 64, wn = (warp & 3) * 32;

    // A loader mapping: two float4 per thread (row, k chunks)
    int arow = tid >> 1, akq = (tid & 1) * 8;
    int mg = m0 + arow;
    int bb = mg >> 10, s = mg & 1023, hh0 = s >> 5, ww0 = s & 31;

    // W loader mapping: two float4 per thread
    int wk = tid >> 4, wn4 = (tid & 15) * 4;

    float acc[4][4][4];
#pragma unroll
    for (int mi = 0; mi < 4; mi++)
#pragma unroll
        for (int nj = 0; nj < 4; nj++)
#pragma unroll
            for (int c = 0; c < 4; c++) acc[mi][nj][c] = 0.f;

    const int NIT = ntaps * 32;
    float4 ra0, ra1, rw0, rw1;

    // ---- loader (it -> staging regs) ----
#define LDG_TILE(IT)                                                        \
    {                                                                       \
        int tap = (IT) >> 5;                                                \
        int k0 = ((IT) & 31) << 4;                                          \
        int dh = 0, dw = 0;                                                 \
        if (ntaps > 1) { int r3 = tap / 3; dh = r3 - 1; dw = tap - r3 * 3 - 1; } \
        int hh = hh0 + dh, ww = ww0 + dw;                                   \
        bool valid = ((unsigned)hh < 32u) && ((unsigned)ww < 32u);          \
        const float* ap = A + ((size_t)((bb << 10) + (hh << 5) + ww)) * CDIM + k0 + akq; \
        ra0 = valid ? *(const float4*)ap : make_float4(0.f, 0.f, 0.f, 0.f); \
        ra1 = valid ? *(const float4*)(ap + 4) : make_float4(0.f, 0.f, 0.f, 0.f); \
        const float* wp = W0 + (size_t)tap * CDIM * CDIM + (size_t)(k0 + wk) * CDIM + n0 + wn4; \
        rw0 = *(const float4*)wp;                                           \
        rw1 = *(const float4*)(wp + 64);                                    \
    }

#define STS_TILE(BUF)                                                       \
    {                                                                       \
        unsigned* ad = &As[BUF][arow * ASTR + akq];                         \
        uint4 u0 = make_uint4(f2tf(ra0.x), f2tf(ra0.y), f2tf(ra0.z), f2tf(ra0.w)); \
        uint4 u1 = make_uint4(f2tf(ra1.x), f2tf(ra1.y), f2tf(ra1.z), f2tf(ra1.w)); \
        *(uint4*)ad = u0;                                                   \
        *(uint4*)(ad + 4) = u1;                                             \
        unsigned* bd = &Bs[BUF][wk * BSTR + wn4];                           \
        uint4 w0 = make_uint4(f2tf(rw0.x), f2tf(rw0.y), f2tf(rw0.z), f2tf(rw0.w)); \
        uint4 w1 = make_uint4(f2tf(rw1.x), f2tf(rw1.y), f2tf(rw1.z), f2tf(rw1.w)); \
        *(uint4*)bd = w0;                                                   \
        *(uint4*)(bd + 64) = w1;                                            \
    }

    LDG_TILE(0);
    STS_TILE(0);
    int cur = 0;

    for (int it = 0; it < NIT; it++) {
        __syncthreads();
        if (it + 1 < NIT) LDG_TILE(it + 1);

        const unsigned* Ab = As[cur];
        const unsigned* Bb = Bs[cur];
#pragma unroll
        for (int ks = 0; ks < 16; ks += 8) {
            unsigned bf[4][2];
#pragma unroll
            for (int nj = 0; nj < 4; nj++) {
                bf[nj][0] = Bb[(ks + t) * BSTR + wn + nj * 8 + g];
                bf[nj][1] = Bb[(ks + t + 4) * BSTR + wn + nj * 8 + g];
            }
#pragma unroll
            for (int mi = 0; mi < 4; mi++) {
                int r0 = (wm + mi * 16 + g) * ASTR;
                int r1 = (wm + mi * 16 + 8 + g) * ASTR;
                unsigned a0 = Ab[r0 + ks + t];
                unsigned a1 = Ab[r1 + ks + t];
                unsigned a2 = Ab[r0 + ks + t + 4];
                unsigned a3 = Ab[r1 + ks + t + 4];
#pragma unroll
                for (int nj = 0; nj < 4; nj++)
                    MMA_TF32(acc[mi][nj], a0, a1, a2, a3, bf[nj][0], bf[nj][1]);
            }
        }
        __syncthreads();
        if (it + 1 < NIT) STS_TILE(1 - cur);
        cur ^= 1;
    }

    // epilogue
#pragma unroll
    for (int mi = 0; mi < 4; mi++) {
        int r0 = m0 + wm + mi * 16 + g;
        int r1 = r0 + 8;
#pragma unroll
        for (int nj = 0; nj < 4; nj++) {
            int col = n0 + wn + nj * 8 + 2 * t;
            float2 v01 = make_float2(acc[mi][nj][0], acc[mi][nj][1]);
            float2 v23 = make_float2(acc[mi][nj][2], acc[mi][nj][3]);
            if (epi) {
                float b0v = bias[col], b1v = bias[col + 1];
                const float* rr0 = residual + (size_t)r0 * CDIM + col;
                const float* rr1 = residual + (size_t)r1 * CDIM + col;
                v01.x += b0v + rr0[0]; v01.y += b1v + rr0[1];
                v23.x += b0v + rr1[0]; v23.y += b1v + rr1[1];
            }
            *(float2*)(C + (size_t)r0 * CDIM + col) = v01;
            *(float2*)(C + (size_t)r1 * CDIM + col) = v23;
        }
    }
}

// ============================================================
// Flash attention: grid (16 qtiles, 8 heads, 16 batch), 256 thr.
// 64x64 tiles, 4x4 fragments, online softmax (fp32).
// ============================================================
#define KPAD 68

__global__ __launch_bounds__(256)
void attn_kernel(const float* __restrict__ q, const float* __restrict__ k,
                 const float* __restrict__ v, float* __restrict__ o) {
    extern __shared__ float sm[];
    float* Qs = sm;
    float* Ks = Qs + 64 * KPAD;
    float* Vs = Ks + 64 * KPAD;
    float* Ps = Vs + 64 * KPAD;

    int qt = blockIdx.x, head = blockIdx.y, b = blockIdx.z;
    int tid = threadIdx.x;
    int ty = tid >> 4, tx = tid & 15;

    size_t base = ((size_t)b * S_TOK) * CDIM + head * 64;
    const float* qb = q + base;
    const float* kb = k + base;
    const float* vb = v + base;

#pragma unroll
    for (int i = 0; i < 4; i++) {
        int idx = tid + i * 256;
        int row = idx >> 4, qq = (idx & 15) * 4;
        *(float4*)&Qs[row * KPAD + qq] =
            *(const float4*)(qb + (size_t)(qt * 64 + row) * CDIM + qq);
    }

    float o_acc[4][4];
    float mi[4], li[4];
#pragma unroll
    for (int i = 0; i < 4; i++) {
        mi[i] = -1e30f; li[i] = 0.f;
#pragma unroll
        for (int j = 0; j < 4; j++) o_acc[i][j] = 0.f;
    }

    for (int kt = 0; kt < 16; kt++) {
        __syncthreads();
#pragma unroll
        for (int i = 0; i < 4; i++) {
            int idx = tid + i * 256;
            int row = idx >> 4, qq = (idx & 15) * 4;
            *(float4*)&Ks[row * KPAD + qq] =
                *(const float4*)(kb + (size_t)(kt * 64 + row) * CDIM + qq);
            *(float4*)&Vs[row * KPAD + qq] =
                *(const float4*)(vb + (size_t)(kt * 64 + row) * CDIM + qq);
        }
        __syncthreads();

        float sv[4][4];
#pragma unroll
        for (int i = 0; i < 4; i++)
#pragma unroll
            for (int j = 0; j < 4; j++) sv[i][j] = 0.f;

        for (int d = 0; d < 64; d += 4) {
            float4 a[4], bb[4];
#pragma unroll
            for (int i = 0; i < 4; i++) a[i] = *(const float4*)&Qs[(ty * 4 + i) * KPAD + d];
#pragma unroll
            for (int j = 0; j < 4; j++) bb[j] = *(const float4*)&Ks[(tx * 4 + j) * KPAD + d];
#pragma unroll
            for (int i = 0; i < 4; i++)
#pragma unroll
                for (int j = 0; j < 4; j++)
                    sv[i][j] += a[i].x * bb[j].x + a[i].y * bb[j].y +
                                a[i].z * bb[j].z + a[i].w * bb[j].w;
        }

#pragma unroll
        for (int i = 0; i < 4; i++) {
            float tmax = -1e30f;
#pragma unroll
            for (int j = 0; j < 4; j++) {
                sv[i][j] *= 0.125f;
                tmax = fmaxf(tmax, sv[i][j]);
            }
#pragma unroll
            for (int off = 8; off >= 1; off >>= 1)
                tmax = fmaxf(tmax, __shfl_xor_sync(0xffffffffu, tmax, off));
            float newm = fmaxf(mi[i], tmax);
            float c = __expf(mi[i] - newm);
            float rs = 0.f;
#pragma unroll
            for (int j = 0; j < 4; j++) {
                sv[i][j] = __expf(sv[i][j] - newm);
                rs += sv[i][j];
            }
#pragma unroll
            for (int off = 8; off >= 1; off >>= 1)
                rs += __shfl_xor_sync(0xffffffffu, rs, off);
            li[i] = li[i] * c + rs;
            mi[i] = newm;
#pragma unroll
            for (int j = 0; j < 4; j++) o_acc[i][j] *= c;
#pragma unroll
            for (int j = 0; j < 4; j++)
                Ps[(ty * 4 + i) * KPAD + tx * 4 + j] = sv[i][j];
        }
        __syncthreads();

        for (int kk = 0; kk < 64; kk += 4) {
            float4 p[4];
#pragma unroll
            for (int i = 0; i < 4; i++) p[i] = *(const float4*)&Ps[(ty * 4 + i) * KPAD + kk];
            float4 v0 = *(const float4*)&Vs[(kk + 0) * KPAD + tx * 4];
            float4 v1 = *(const float4*)&Vs[(kk + 1) * KPAD + tx * 4];
            float4 v2 = *(const float4*)&Vs[(kk + 2) * KPAD + tx * 4];
            float4 v3 = *(const float4*)&Vs[(kk + 3) * KPAD + tx * 4];
#pragma unroll
            for (int i = 0; i < 4; i++) {
                o_acc[i][0] += p[i].x * v0.x + p[i].y * v1.x + p[i].z * v2.x + p[i].w * v3.x;
                o_acc[i][1] += p[i].x * v0.y + p[i].y * v1.y + p[i].z * v2.y + p[i].w * v3.y;
                o_acc[i][2] += p[i].x * v0.z + p[i].y * v1.z + p[i].z * v2.z + p[i].w * v3.z;
                o_acc[i][3] += p[i].x * v0.w + p[i].y * v1.w + p[i].z * v2.w + p[i].w * v3.w;
            }
        }
    }

#pragma unroll
    for (int i = 0; i < 4; i++) {
        float inv = 1.f / li[i];
        int srow = qt * 64 + ty * 4 + i;
        float* orow = o + ((size_t)b * S_TOK + srow) * CDIM + head * 64 + tx * 4;
        float4 val = make_float4(o_acc[i][0] * inv, o_acc[i][1] * inv,
                                 o_acc[i][2] * inv, o_acc[i][3] * inv);
        *(float4*)orow = val;
    }
}

// ============================================================
// launch
// ============================================================
extern "C" void kernel_launch(void* const* d_in, const int* in_sizes, int n_in,
                              void* d_out, int out_size) {
    const float* x       = (const float*)d_in[0];
    const float* gamma   = (const float*)d_in[1];
    const float* beta    = (const float*)d_in[2];
    const float* wq      = (const float*)d_in[3];
    const float* wk      = (const float*)d_in[4];
    const float* wv      = (const float*)d_in[5];
    const float* conv_w  = (const float*)d_in[6];
    const float* conv_b  = (const float*)d_in[7];
    float* out = (float*)d_out;

    float *xn, *qb, *kb, *vb, *ab;
    cudaGetSymbolAddress((void**)&xn, g_xn);
    cudaGetSymbolAddress((void**)&qb, g_q);
    cudaGetSymbolAddress((void**)&kb, g_k);
    cudaGetSymbolAddress((void**)&vb, g_v);
    cudaGetSymbolAddress((void**)&ab, g_attn);

    // GroupNorm
    gn_kernel<<<512, 256>>>(x, gamma, beta, xn);

    // QKV projections (tf32 tensor cores)
    dim3 ggrid(CDIM / 128, NTOK / 128);
    gemm_tf32<<<ggrid, 256>>>(xn, wq, qb, 1, nullptr, nullptr, 0);
    gemm_tf32<<<ggrid, 256>>>(xn, wk, kb, 1, nullptr, nullptr, 0);
    gemm_tf32<<<ggrid, 256>>>(xn, wv, vb, 1, nullptr, nullptr, 0);

    // Attention (fp32, unchanged this round)
    cudaFuncSetAttribute(attn_kernel, cudaFuncAttributeMaxDynamicSharedMemorySize,
                         4 * 64 * KPAD * (int)sizeof(float));
    attn_kernel<<<dim3(16, 8, 16), 256, 4 * 64 * KPAD * sizeof(float)>>>(qb, kb, vb, ab);

    // 3x3 conv: ONE fused kernel, 9 taps accumulated in registers,
    // bias + residual fused into the epilogue.
    gemm_tf32<<<ggrid, 256>>>(ab, conv_w, out, 9, conv_b, x, 1);
}

// round 3
// speedup vs baseline: 4.2464x; 4.2437x over previous
#include <cuda_runtime.h>
#include <math.h>

#define S_TOK 1024
#define CDIM  512
#define NTOK  16384   // B * S_TOK

// ---- scratch (static device globals; no runtime allocation) ----
__device__ float g_xn  [NTOK * CDIM];
__device__ float g_q   [NTOK * CDIM];
__device__ float g_k   [NTOK * CDIM];
__device__ float g_v   [NTOK * CDIM];
__device__ float g_attn[NTOK * CDIM];

// ============================================================
// GroupNorm
// ============================================================
__global__ void gn_kernel(const float* __restrict__ x,
                          const float* __restrict__ gamma,
                          const float* __restrict__ beta,
                          float* __restrict__ xn) {
    int bg = blockIdx.x;
    int b = bg >> 5, g = bg & 31;
    const float* xb  = x  + (size_t)b * S_TOK * CDIM + g * 16;
    float*       xnb = xn + (size_t)b * S_TOK * CDIM + g * 16;

    float sum = 0.f, sumsq = 0.f;
    for (int t = threadIdx.x; t < 16384; t += 256) {
        int s = t >> 4, c = t & 15;
        float v = xb[s * CDIM + c];
        sum += v; sumsq += v * v;
    }
    __shared__ float red[256], red2[256];
    red[threadIdx.x] = sum; red2[threadIdx.x] = sumsq;
    __syncthreads();
    for (int off = 128; off > 0; off >>= 1) {
        if (threadIdx.x < off) {
            red[threadIdx.x]  += red[threadIdx.x + off];
            red2[threadIdx.x] += red2[threadIdx.x + off];
        }
        __syncthreads();
    }
    float mean = red[0] * (1.f / 16384.f);
    float var  = red2[0] * (1.f / 16384.f) - mean * mean;
    float inv  = rsqrtf(var + 1e-5f);

    for (int t = threadIdx.x; t < 16384; t += 256) {
        int s = t >> 4, c = t & 15;
        float v = xb[s * CDIM + c];
        xnb[s * CDIM + c] = (v - mean) * inv * gamma[g * 16 + c] + beta[g * 16 + c];
    }
}

// ============================================================
// TF32 mma helpers
// ============================================================
#define MMA_TF32(d, a0, a1, a2, a3, b0, b1)                                 \
    asm volatile(                                                           \
        "mma.sync.aligned.m16n8k8.row.col.f32.tf32.tf32.f32 "               \
        "{%0,%1,%2,%3}, {%4,%5,%6,%7}, {%8,%9}, {%0,%1,%2,%3};\n"           \
        : "+f"(d[0]), "+f"(d[1]), "+f"(d[2]), "+f"(d[3])                    \
        : "r"(a0), "r"(a1), "r"(a2), "r"(a3), "r"(b0), "r"(b1))

#define CP_ASYNC16(daddr, gptr, sz)                                         \
    asm volatile("cp.async.cg.shared.global [%0], [%1], 16, %2;\n"          \
                 :: "r"(daddr), "l"(gptr), "r"(sz))
#define CP_COMMIT() asm volatile("cp.async.commit_group;\n")
#define CP_WAIT1()  asm volatile("cp.async.wait_group 1;\n")

// ============================================================
// TF32 GEMM with cp.async pipeline.
//   C[16384, 512] = sum_tap Ashift[16384,512] @ W_tap[512,512]
// 128x128 tile, BK=32, 2-stage cp.async double buffer, 8 warps
// (64x32 warp tiles), raw fp32 fed to tf32 mma (HW truncation).
// ============================================================
#define ASTR 36    // A smem stride: banks 4g+t conflict-free
#define BSTR 136   // B smem stride: banks 8t+g conflict-free

__global__ __launch_bounds__(256)
void gemm_tf32(const float* __restrict__ A, const float* __restrict__ W0,
               float* __restrict__ C, int ntaps,
               const float* __restrict__ bias,
               const float* __restrict__ residual, int epi) {
    extern __shared__ float smem[];
    float* As = smem;                       // [2][128*ASTR]
    float* Bs = smem + 2 * 128 * ASTR;      // [2][32*BSTR]
    const int ASZ = 128 * ASTR, BSZ = 32 * BSTR;

    int tid = threadIdx.x, warp = tid >> 5, lane = tid & 31;
    int g = lane >> 2, t = lane & 3;
    int m0 = blockIdx.y * 128, n0 = blockIdx.x * 128;
    int wm = (warp >> 2) * 64, wn = (warp & 3) * 32;

    // A loader: rows ar+32p, k chunk akofs
    int ar = tid >> 3, akofs = (tid & 7) * 4;
    int bidx[4], hh0[4], ww0[4];
#pragma unroll
    for (int p = 0; p < 4; p++) {
        int mg = m0 + ar + 32 * p;
        bidx[p] = mg >> 10;
        int s = mg & 1023;
        hh0[p] = s >> 5; ww0[p] = s & 31;
    }
    // B loader: k rows bkr+8p, n chunk bnofs
    int bkr = tid >> 5, bnofs = (tid & 31) * 4;

    float acc[4][4][4];
#pragma unroll
    for (int mi = 0; mi < 4; mi++)
#pragma unroll
        for (int nj = 0; nj < 4; nj++)
#pragma unroll
            for (int c = 0; c < 4; c++) acc[mi][nj][c] = 0.f;

    const int NIT = ntaps * 16;

#define LOAD_TILE(IT, ST)                                                   \
    {                                                                       \
        int tap = (IT) >> 4;                                                \
        int k0 = ((IT) & 15) << 5;                                          \
        int dh = 0, dw = 0;                                                 \
        if (ntaps > 1) { int r3 = tap / 3; dh = r3 - 1; dw = tap - r3 * 3 - 1; } \
        float* as = As + (ST) * ASZ;                                        \
        _Pragma("unroll")                                                   \
        for (int p = 0; p < 4; p++) {                                       \
            int hh = hh0[p] + dh, ww = ww0[p] + dw;                         \
            bool valid = ((unsigned)hh < 32u) && ((unsigned)ww < 32u);      \
            const float* gp = A + ((size_t)((bidx[p] << 10) + (hh << 5) + ww)) * CDIM + k0 + akofs; \
            unsigned da = (unsigned)__cvta_generic_to_shared(as + (ar + 32 * p) * ASTR + akofs); \
            CP_ASYNC16(da, gp, valid ? 16 : 0);                             \
        }                                                                   \
        float* bs = Bs + (ST) * BSZ;                                        \
        const float* wbase = W0 + (size_t)tap * CDIM * CDIM + (size_t)k0 * CDIM + n0; \
        _Pragma("unroll")                                                   \
        for (int p = 0; p < 4; p++) {                                       \
            int kr = bkr + 8 * p;                                           \
            const float* gp = wbase + (size_t)kr * CDIM + bnofs;            \
            unsigned da = (unsigned)__cvta_generic_to_shared(bs + kr * BSTR + bnofs); \
            CP_ASYNC16(da, gp, 16);                                         \
        }                                                                   \
        CP_COMMIT();                                                        \
    }

    LOAD_TILE(0, 0);
    LOAD_TILE(1, 1);

    for (int it = 0; it < NIT; it++) {
        int st = it & 1;
        CP_WAIT1();
        __syncthreads();
        const float* Ab = As + st * ASZ;
        const float* Bb = Bs + st * BSZ;
#pragma unroll
        for (int ks = 0; ks < 4; ks++) {
            unsigned bf[4][2];
#pragma unroll
            for (int nj = 0; nj < 4; nj++) {
                bf[nj][0] = __float_as_uint(Bb[(ks * 8 + t) * BSTR + wn + nj * 8 + g]);
                bf[nj][1] = __float_as_uint(Bb[(ks * 8 + t + 4) * BSTR + wn + nj * 8 + g]);
            }
#pragma unroll
            for (int mi = 0; mi < 4; mi++) {
                int r0 = (wm + mi * 16 + g) * ASTR;
                int r1 = r0 + 8 * ASTR;
                unsigned a0 = __float_as_uint(Ab[r0 + ks * 8 + t]);
                unsigned a1 = __float_as_uint(Ab[r1 + ks * 8 + t]);
                unsigned a2 = __float_as_uint(Ab[r0 + ks * 8 + t + 4]);
                unsigned a3 = __float_as_uint(Ab[r1 + ks * 8 + t + 4]);
#pragma unroll
                for (int nj = 0; nj < 4; nj++)
                    MMA_TF32(acc[mi][nj], a0, a1, a2, a3, bf[nj][0], bf[nj][1]);
            }
        }
        __syncthreads();
        if (it + 2 < NIT) LOAD_TILE(it + 2, st);
    }

    // epilogue
#pragma unroll
    for (int mi = 0; mi < 4; mi++) {
        int r0 = m0 + wm + mi * 16 + g;
        int r1 = r0 + 8;
#pragma unroll
        for (int nj = 0; nj < 4; nj++) {
            int col = n0 + wn + nj * 8 + 2 * t;
            float2 v01 = make_float2(acc[mi][nj][0], acc[mi][nj][1]);
            float2 v23 = make_float2(acc[mi][nj][2], acc[mi][nj][3]);
            if (epi) {
                float b0v = bias[col], b1v = bias[col + 1];
                const float* rr0 = residual + (size_t)r0 * CDIM + col;
                const float* rr1 = residual + (size_t)r1 * CDIM + col;
                v01.x += b0v + rr0[0]; v01.y += b1v + rr0[1];
                v23.x += b0v + rr1[0]; v23.y += b1v + rr1[1];
            }
            *(float2*)(C + (size_t)r0 * CDIM + col) = v01;
            *(float2*)(C + (size_t)r1 * CDIM + col) = v23;
        }
    }
}

// ============================================================
// Tensor-core flash attention (tf32 mma).
// Block: 128 q rows, one (b, head). 8 warps, each owns 16 q rows
// so online softmax is warp-local. K/V tiles of 64.
// Q/K/P smem stride 68 (banks 4g+t), V stride 72 (banks 8t+g).
// ============================================================
#define QSTR 68
#define VSTR 72

__global__ __launch_bounds__(256)
void attn_kernel(const float* __restrict__ q, const float* __restrict__ k,
                 const float* __restrict__ v, float* __restrict__ o) {
    extern __shared__ float sm[];
    float* Qs = sm;                       // [128][QSTR]
    float* Ks = Qs + 128 * QSTR;          // [64][QSTR]
    float* Vs = Ks + 64 * QSTR;           // [64][VSTR]
    float* Ps = Vs + 64 * VSTR;           // [128][QSTR]

    int qt = blockIdx.x, head = blockIdx.y, b = blockIdx.z;
    int tid = threadIdx.x, warp = tid >> 5, lane = tid & 31;
    int g = lane >> 2, t = lane & 3;

    size_t base = ((size_t)b * S_TOK) * CDIM + head * 64;
    const float* qb = q + base;
    const float* kb = k + base;
    const float* vb = v + base;

    // load Q tile [128 x 64]
#pragma unroll
    for (int i = 0; i < 8; i++) {
        int idx = tid + i * 256;
        int row = idx >> 4, c4 = (idx & 15) * 4;
        *(float4*)&Qs[row * QSTR + c4] =
            *(const float4*)(qb + (size_t)(qt * 128 + row) * CDIM + c4);
    }

    float o_acc[8][4];
    float mi0 = -1e30f, mi1 = -1e30f, li0 = 0.f, li1 = 0.f;
#pragma unroll
    for (int dj = 0; dj < 8; dj++)
#pragma unroll
        for (int c = 0; c < 4; c++) o_acc[dj][c] = 0.f;

    int qrow = warp * 16;   // warp's q-row base within tile

    for (int kt = 0; kt < 16; kt++) {
        __syncthreads();
        // load K,V tiles [64 x 64]
#pragma unroll
        for (int i = 0; i < 4; i++) {
            int idx = tid + i * 256;
            int row = idx >> 4, c4 = (idx & 15) * 4;
            const float4 kv = *(const float4*)(kb + (size_t)(kt * 64 + row) * CDIM + c4);
            const float4 vv = *(const float4*)(vb + (size_t)(kt * 64 + row) * CDIM + c4);
            *(float4*)&Ks[row * QSTR + c4] = kv;
            *(float4*)&Vs[row * VSTR + c4] = vv;
        }
        __syncthreads();

        // S = Q @ K^T : warp computes [16 x 64]
        float sv[8][4];
#pragma unroll
        for (int nj = 0; nj < 8; nj++)
#pragma unroll
            for (int c = 0; c < 4; c++) sv[nj][c] = 0.f;

#pragma unroll
        for (int ks = 0; ks < 8; ks++) {
            int r0 = (qrow + g) * QSTR, r1 = r0 + 8 * QSTR;
            unsigned a0 = __float_as_uint(Qs[r0 + ks * 8 + t]);
            unsigned a1 = __float_as_uint(Qs[r1 + ks * 8 + t]);
            unsigned a2 = __float_as_uint(Qs[r0 + ks * 8 + t + 4]);
            unsigned a3 = __float_as_uint(Qs[r1 + ks * 8 + t + 4]);
#pragma unroll
            for (int nj = 0; nj < 8; nj++) {
                unsigned b0 = __float_as_uint(Ks[(nj * 8 + g) * QSTR + ks * 8 + t]);
                unsigned b1 = __float_as_uint(Ks[(nj * 8 + g) * QSTR + ks * 8 + t + 4]);
                MMA_TF32(sv[nj], a0, a1, a2, a3, b0, b1);
            }
        }

        // online softmax: thread owns rows (g) and (g+8) of warp tile
        float m0 = -1e30f, m1 = -1e30f;
#pragma unroll
        for (int nj = 0; nj < 8; nj++) {
#pragma unroll
            for (int c = 0; c < 4; c++) sv[nj][c] *= 0.125f;
            m0 = fmaxf(m0, fmaxf(sv[nj][0], sv[nj][1]));
            m1 = fmaxf(m1, fmaxf(sv[nj][2], sv[nj][3]));
        }
        m0 = fmaxf(m0, __shfl_xor_sync(0xffffffffu, m0, 1));
        m0 = fmaxf(m0, __shfl_xor_sync(0xffffffffu, m0, 2));
        m1 = fmaxf(m1, __shfl_xor_sync(0xffffffffu, m1, 1));
        m1 = fmaxf(m1, __shfl_xor_sync(0xffffffffu, m1, 2));
        float nm0 = fmaxf(mi0, m0), nm1 = fmaxf(mi1, m1);
        float cr0 = __expf(mi0 - nm0), cr1 = __expf(mi1 - nm1);
        float s0 = 0.f, s1 = 0.f;
#pragma unroll
        for (int nj = 0; nj < 8; nj++) {
            sv[nj][0] = __expf(sv[nj][0] - nm0);
            sv[nj][1] = __expf(sv[nj][1] - nm0);
            sv[nj][2] = __expf(sv[nj][2] - nm1);
            sv[nj][3] = __expf(sv[nj][3] - nm1);
            s0 += sv[nj][0] + sv[nj][1];
            s1 += sv[nj][2] + sv[nj][3];
        }
        s0 += __shfl_xor_sync(0xffffffffu, s0, 1);
        s0 += __shfl_xor_sync(0xffffffffu, s0, 2);
        s1 += __shfl_xor_sync(0xffffffffu, s1, 1);
        s1 += __shfl_xor_sync(0xffffffffu, s1, 2);
        li0 = li0 * cr0 + s0; li1 = li1 * cr1 + s1;
        mi0 = nm0; mi1 = nm1;
#pragma unroll
        for (int dj = 0; dj < 8; dj++) {
            o_acc[dj][0] *= cr0; o_acc[dj][1] *= cr0;
            o_acc[dj][2] *= cr1; o_acc[dj][3] *= cr1;
        }

        // stage P to (warp-private) smem for A-fragment reload
        int pr0 = (qrow + g) * QSTR, pr1 = pr0 + 8 * QSTR;
#pragma unroll
        for (int nj = 0; nj < 8; nj++) {
            *(float2*)&Ps[pr0 + nj * 8 + 2 * t] = make_float2(sv[nj][0], sv[nj][1]);
            *(float2*)&Ps[pr1 + nj * 8 + 2 * t] = make_float2(sv[nj][2], sv[nj][3]);
        }
        __syncwarp();

        // O += P @ V : warp computes [16 x 64]
#pragma unroll
        for (int ks = 0; ks < 8; ks++) {
            unsigned a0 = __float_as_uint(Ps[pr0 + ks * 8 + t]);
            unsigned a1 = __float_as_uint(Ps[pr1 + ks * 8 + t]);
            unsigned a2 = __float_as_uint(Ps[pr0 + ks * 8 + t + 4]);
            unsigned a3 = __float_as_uint(Ps[pr1 + ks * 8 + t + 4]);
#pragma unroll
            for (int dj = 0; dj < 8; dj++) {
                unsigned b0 = __float_as_uint(Vs[(ks * 8 + t) * VSTR + dj * 8 + g]);
                unsigned b1 = __float_as_uint(Vs[(ks * 8 + t + 4) * VSTR + dj * 8 + g]);
                MMA_TF32(o_acc[dj], a0, a1, a2, a3, b0, b1);
            }
        }
    }

    // normalize + write: rows qt*128 + qrow + g (+8)
    float inv0 = 1.f / li0, inv1 = 1.f / li1;
    int gr0 = qt * 128 + qrow + g;
    float* or0 = o + ((size_t)b * S_TOK + gr0) * CDIM + head * 64;
    float* or1 = or0 + 8 * CDIM;
#pragma unroll
    for (int dj = 0; dj < 8; dj++) {
        *(float2*)(or0 + dj * 8 + 2 * t) =
            make_float2(o_acc[dj][0] * inv0, o_acc[dj][1] * inv0);
        *(float2*)(or1 + dj * 8 + 2 * t) =
            make_float2(o_acc[dj][2] * inv1, o_acc[dj][3] * inv1);
    }
}

// ============================================================
// launch
// ============================================================
extern "C" void kernel_launch(void* const* d_in, const int* in_sizes, int n_in,
                              void* d_out, int out_size) {
    const float* x       = (const float*)d_in[0];
    const float* gamma   = (const float*)d_in[1];
    const float* beta    = (const float*)d_in[2];
    const float* wq      = (const float*)d_in[3];
    const float* wk      = (const float*)d_in[4];
    const float* wv      = (const float*)d_in[5];
    const float* conv_w  = (const float*)d_in[6];
    const float* conv_b  = (const float*)d_in[7];
    float* out = (float*)d_out;

    float *xn, *qb, *kb, *vb, *ab;
    cudaGetSymbolAddress((void**)&xn, g_xn);
    cudaGetSymbolAddress((void**)&qb, g_q);
    cudaGetSymbolAddress((void**)&kb, g_k);
    cudaGetSymbolAddress((void**)&vb, g_v);
    cudaGetSymbolAddress((void**)&ab, g_attn);

    const int gemm_smem = (2 * 128 * ASTR + 2 * 32 * BSTR) * (int)sizeof(float);
    const int attn_smem = (128 * QSTR + 64 * QSTR + 64 * VSTR + 128 * QSTR) * (int)sizeof(float);
    cudaFuncSetAttribute(gemm_tf32, cudaFuncAttributeMaxDynamicSharedMemorySize, gemm_smem);
    cudaFuncSetAttribute(attn_kernel, cudaFuncAttributeMaxDynamicSharedMemorySize, attn_smem);

    // GroupNorm
    gn_kernel<<<512, 256>>>(x, gamma, beta, xn);

    // QKV projections
    dim3 ggrid(CDIM / 128, NTOK / 128);
    gemm_tf32<<<ggrid, 256, gemm_smem>>>(xn, wq, qb, 1, nullptr, nullptr, 0);
    gemm_tf32<<<ggrid, 256, gemm_smem>>>(xn, wk, kb, 1, nullptr, nullptr, 0);
    gemm_tf32<<<ggrid, 256, gemm_smem>>>(xn, wv, vb, 1, nullptr, nullptr, 0);

    // Attention (tf32 tensor cores)
    attn_kernel<<<dim3(8, 8, 16), 256, attn_smem>>>(qb, kb, vb, ab);

    // 3x3 conv: one fused 9-tap GEMM with bias + residual epilogue
    gemm_tf32<<<ggrid, 256, gemm_smem>>>(ab, conv_w, out, 9, conv_b, x, 1);
}

// round 4
// speedup vs baseline: 6.0022x; 1.4135x over previous
#include <cuda_runtime.h>
#include <cuda_bf16.h>
#include <math.h>

#define S_TOK 1024
#define CDIM  512
#define NTOK  16384   // B * S_TOK

// ---- scratch (static device globals; no runtime allocation) ----
__device__ __nv_bfloat16 g_xn_h  [NTOK * CDIM];
__device__ __nv_bfloat16 g_attn_h[NTOK * CDIM];
__device__ __nv_bfloat16 g_wt    [12 * CDIM * CDIM];  // [z][n][k] bf16
__device__ float g_q[NTOK * CDIM];
__device__ float g_k[NTOK * CDIM];
__device__ float g_v[NTOK * CDIM];

// ============================================================
// GroupNorm -> bf16 output
// ============================================================
__global__ void gn_kernel(const float* __restrict__ x,
                          const float* __restrict__ gamma,
                          const float* __restrict__ beta,
                          __nv_bfloat16* __restrict__ xn) {
    int bg = blockIdx.x;
    int b = bg >> 5, g = bg & 31;
    const float* xb = x + (size_t)b * S_TOK * CDIM + g * 16;
    __nv_bfloat16* xo = xn + (size_t)b * S_TOK * CDIM + g * 16;

    float sum = 0.f, sumsq = 0.f;
    for (int task = threadIdx.x; task < 4096; task += 256) {
        int s = task >> 2, c4 = (task & 3) * 4;
        float4 v = *(const float4*)(xb + s * CDIM + c4);
        sum += v.x + v.y + v.z + v.w;
        sumsq += v.x * v.x + v.y * v.y + v.z * v.z + v.w * v.w;
    }
    __shared__ float red[256], red2[256];
    red[threadIdx.x] = sum; red2[threadIdx.x] = sumsq;
    __syncthreads();
    for (int off = 128; off > 0; off >>= 1) {
        if (threadIdx.x < off) {
            red[threadIdx.x]  += red[threadIdx.x + off];
            red2[threadIdx.x] += red2[threadIdx.x + off];
        }
        __syncthreads();
    }
    float mean = red[0] * (1.f / 16384.f);
    float var  = red2[0] * (1.f / 16384.f) - mean * mean;
    float inv  = rsqrtf(var + 1e-5f);

    for (int task = threadIdx.x; task < 4096; task += 256) {
        int s = task >> 2, c4 = (task & 3) * 4;
        float4 v = *(const float4*)(xb + s * CDIM + c4);
        float4 ga = *(const float4*)(gamma + g * 16 + c4);
        float4 be = *(const float4*)(beta  + g * 16 + c4);
        float o0 = (v.x - mean) * inv * ga.x + be.x;
        float o1 = (v.y - mean) * inv * ga.y + be.y;
        float o2 = (v.z - mean) * inv * ga.z + be.z;
        float o3 = (v.w - mean) * inv * ga.w + be.w;
        __nv_bfloat162 p0 = make_bfloat162(__float2bfloat16(o0), __float2bfloat16(o1));
        __nv_bfloat162 p1 = make_bfloat162(__float2bfloat16(o2), __float2bfloat16(o3));
        uint2 pk = make_uint2(*(unsigned*)&p0, *(unsigned*)&p1);
        *(uint2*)(xo + s * CDIM + c4) = pk;
    }
}

// ============================================================
// Weight transpose + convert: out[z][n][k] = bf16(src_z[k][n])
// z: 0..2 = wq,wk,wv; 3..11 = conv taps
// ============================================================
__global__ void wt_kernel(const float* __restrict__ wq, const float* __restrict__ wk,
                          const float* __restrict__ wv, const float* __restrict__ cw,
                          __nv_bfloat16* __restrict__ out) {
    __shared__ float tile[32][33];
    int z = blockIdx.z;
    const float* src = (z == 0) ? wq : (z == 1) ? wk : (z == 2) ? wv
                       : cw + (size_t)(z - 3) * CDIM * CDIM;
    __nv_bfloat16* dst = out + (size_t)z * CDIM * CDIM;
    int k0 = blockIdx.y * 32, n0 = blockIdx.x * 32;
    int tx = threadIdx.x, ty = threadIdx.y;
#pragma unroll
    for (int i = 0; i < 32; i += 8)
        tile[ty + i][tx] = src[(size_t)(k0 + ty + i) * CDIM + n0 + tx];
    __syncthreads();
#pragma unroll
    for (int i = 0; i < 32; i += 8)
        dst[(size_t)(n0 + ty + i) * CDIM + k0 + tx] = __float2bfloat16(tile[tx][ty + i]);
}

// ============================================================
// mma / ldmatrix / cp.async helpers
// ============================================================
#define MMA_BF16(d, a, b0, b1)                                              \
    asm volatile(                                                           \
        "mma.sync.aligned.m16n8k16.row.col.f32.bf16.bf16.f32 "              \
        "{%0,%1,%2,%3}, {%4,%5,%6,%7}, {%8,%9}, {%0,%1,%2,%3};\n"           \
        : "+f"(d[0]), "+f"(d[1]), "+f"(d[2]), "+f"(d[3])                    \
        : "r"(a[0]), "r"(a[1]), "r"(a[2]), "r"(a[3]), "r"(b0), "r"(b1))

#define MMA_TF32(d, a0, a1, a2, a3, b0, b1)                                 \
    asm volatile(                                                           \
        "mma.sync.aligned.m16n8k8.row.col.f32.tf32.tf32.f32 "               \
        "{%0,%1,%2,%3}, {%4,%5,%6,%7}, {%8,%9}, {%0,%1,%2,%3};\n"           \
        : "+f"(d[0]), "+f"(d[1]), "+f"(d[2]), "+f"(d[3])                    \
        : "r"(a0), "r"(a1), "r"(a2), "r"(a3), "r"(b0), "r"(b1))

#define LDSM4(r, addr)                                                      \
    asm volatile("ldmatrix.sync.aligned.m8n8.x4.shared.b16 {%0,%1,%2,%3}, [%4];\n" \
                 : "=r"(r[0]), "=r"(r[1]), "=r"(r[2]), "=r"(r[3]) : "r"(addr))

#define CP_ASYNC16(daddr, gptr, sz)                                         \
    asm volatile("cp.async.cg.shared.global [%0], [%1], 16, %2;\n"          \
                 :: "r"(daddr), "l"(gptr), "r"(sz))
#define CP_COMMIT() asm volatile("cp.async.commit_group;\n")
#define CP_WAIT1()  asm volatile("cp.async.wait_group 1;\n")

// ============================================================
// BF16 GEMM: C[16384,512] = sum_tap Ashift[16384,512] @ Wt_tap^T
// A: [m][k] bf16, Wt: [tap][n][k] bf16 (pre-transposed).
// 128x128 tile, BK=32, 3-stage cp.async ring, 8 warps (64x32),
// ldmatrix.x4 frags, smem row stride 80B (conflict-free LDSM).
// ============================================================
#define STG_BYTES 20480   // per stage: A 128*80 + B 128*80

__global__ __launch_bounds__(256)
void gemm_bf16(const __nv_bfloat16* __restrict__ A,
               const __nv_bfloat16* __restrict__ Wt,
               float* __restrict__ C, int ntaps,
               const float* __restrict__ bias,
               const float* __restrict__ residual, int epi) {
    extern __shared__ char smem[];

    int tid = threadIdx.x, warp = tid >> 5, lane = tid & 31;
    int g = lane >> 2, t = lane & 3;
    int m0 = blockIdx.y * 128, n0 = blockIdx.x * 128;
    int wm = (warp >> 2) * 64, wn = (warp & 3) * 32;

    // loader mapping: 512 16B-chunks per operand, 2 per thread
    int lrow = tid >> 2, lchunk = tid & 3;
    int bidx[2], hh0[2], ww0[2];
#pragma unroll
    for (int p = 0; p < 2; p++) {
        int mg = m0 + lrow + 64 * p;
        bidx[p] = mg >> 10;
        int s = mg & 1023;
        hh0[p] = s >> 5; ww0[p] = s & 31;
    }

    float acc[4][4][4];
#pragma unroll
    for (int mi = 0; mi < 4; mi++)
#pragma unroll
        for (int nj = 0; nj < 4; nj++)
#pragma unroll
            for (int c = 0; c < 4; c++) acc[mi][nj][c] = 0.f;

    const int NIT = ntaps * 16;

#define LOAD_TILE(IT, ST)                                                   \
    {                                                                       \
        int tap = (IT) >> 4;                                                \
        int k0 = ((IT) & 15) << 5;                                          \
        int dh = 0, dw = 0;                                                 \
        if (ntaps > 1) { int r3 = tap / 3; dh = r3 - 1; dw = tap - r3 * 3 - 1; } \
        char* as = smem + (ST) * STG_BYTES;                                 \
        char* bs = as + 10240;                                              \
        _Pragma("unroll")                                                   \
        for (int p = 0; p < 2; p++) {                                       \
            int hh = hh0[p] + dh, ww = ww0[p] + dw;                         \
            bool valid = ((unsigned)hh < 32u) && ((unsigned)ww < 32u);      \
            const __nv_bfloat16* gp = A + (size_t)((bidx[p] << 10) + (hh << 5) + ww) * CDIM + k0 + lchunk * 8; \
            unsigned da = (unsigned)__cvta_generic_to_shared(as + (lrow + 64 * p) * 80 + lchunk * 16); \
            CP_ASYNC16(da, gp, valid ? 16 : 0);                             \
        }                                                                   \
        const __nv_bfloat16* wb = Wt + (size_t)tap * CDIM * CDIM + (size_t)n0 * CDIM + k0; \
        _Pragma("unroll")                                                   \
        for (int p = 0; p < 2; p++) {                                       \
            const __nv_bfloat16* gp = wb + (size_t)(lrow + 64 * p) * CDIM + lchunk * 8; \
            unsigned da = (unsigned)__cvta_generic_to_shared(bs + (lrow + 64 * p) * 80 + lchunk * 16); \
            CP_ASYNC16(da, gp, 16);                                         \
        }                                                                   \
        CP_COMMIT();                                                        \
    }

    LOAD_TILE(0, 0);
    LOAD_TILE(1, 1);

    // ldmatrix lane address components (in halves)
    int arow_f = wm + (lane & 15);
    int akoff  = (lane >> 4) * 8;
    int brow_f = wn + (lane & 7) + ((lane >> 4) << 3);
    int bkoff  = ((lane >> 3) & 1) * 8;

    int st = 0;
    for (int it = 0; it < NIT; it++) {
        CP_WAIT1();
        __syncthreads();
        char* as = smem + st * STG_BYTES;
        char* bs = as + 10240;
        unsigned abase = (unsigned)__cvta_generic_to_shared(as);
        unsigned bbase = (unsigned)__cvta_generic_to_shared(bs);

#pragma unroll
        for (int ks = 0; ks < 2; ks++) {
            unsigned bfr[2][4];
#pragma unroll
            for (int njp = 0; njp < 2; njp++) {
                unsigned addr = bbase + ((brow_f + njp * 16) * 40 + ks * 16 + bkoff) * 2;
                LDSM4(bfr[njp], addr);
            }
#pragma unroll
            for (int mi = 0; mi < 4; mi++) {
                unsigned af[4];
                unsigned addr = abase + ((arow_f + mi * 16) * 40 + ks * 16 + akoff) * 2;
                LDSM4(af, addr);
                MMA_BF16(acc[mi][0], af, bfr[0][0], bfr[0][1]);
                MMA_BF16(acc[mi][1], af, bfr[0][2], bfr[0][3]);
                MMA_BF16(acc[mi][2], af, bfr[1][0], bfr[1][1]);
                MMA_BF16(acc[mi][3], af, bfr[1][2], bfr[1][3]);
            }
        }
        if (it + 2 < NIT) {
            int wst = st + 2; if (wst >= 3) wst -= 3;
            LOAD_TILE(it + 2, wst);
        }
        st++; if (st == 3) st = 0;
    }

    // epilogue (fp32 accum -> fp32 C)
#pragma unroll
    for (int mi = 0; mi < 4; mi++) {
        int r0 = m0 + wm + mi * 16 + g;
        int r1 = r0 + 8;
#pragma unroll
        for (int nj = 0; nj < 4; nj++) {
            int col = n0 + wn + nj * 8 + 2 * t;
            float2 v01 = make_float2(acc[mi][nj][0], acc[mi][nj][1]);
            float2 v23 = make_float2(acc[mi][nj][2], acc[mi][nj][3]);
            if (epi) {
                float b0v = bias[col], b1v = bias[col + 1];
                const float* rr0 = residual + (size_t)r0 * CDIM + col;
                const float* rr1 = residual + (size_t)r1 * CDIM + col;
                v01.x += b0v + rr0[0]; v01.y += b1v + rr0[1];
                v23.x += b0v + rr1[0]; v23.y += b1v + rr1[1];
            }
            *(float2*)(C + (size_t)r0 * CDIM + col) = v01;
            *(float2*)(C + (size_t)r1 * CDIM + col) = v23;
        }
    }
}

// ============================================================
// Tensor-core flash attention (tf32 mma), bf16 output.
// ============================================================
#define QSTR 68
#define VSTR 72

__global__ __launch_bounds__(256)
void attn_kernel(const float* __restrict__ q, const float* __restrict__ k,
                 const float* __restrict__ v, __nv_bfloat16* __restrict__ o) {
    extern __shared__ float sm[];
    float* Qs = sm;
    float* Ks = Qs + 128 * QSTR;
    float* Vs = Ks + 64 * QSTR;
    float* Ps = Vs + 64 * VSTR;

    int qt = blockIdx.x, head = blockIdx.y, b = blockIdx.z;
    int tid = threadIdx.x, warp = tid >> 5, lane = tid & 31;
    int g = lane >> 2, t = lane & 3;

    size_t base = ((size_t)b * S_TOK) * CDIM + head * 64;
    const float* qb = q + base;
    const float* kb = k + base;
    const float* vb = v + base;

#pragma unroll
    for (int i = 0; i < 8; i++) {
        int idx = tid + i * 256;
        int row = idx >> 4, c4 = (idx & 15) * 4;
        *(float4*)&Qs[row * QSTR + c4] =
            *(const float4*)(qb + (size_t)(qt * 128 + row) * CDIM + c4);
    }

    float o_acc[8][4];
    float mi0 = -1e30f, mi1 = -1e30f, li0 = 0.f, li1 = 0.f;
#pragma unroll
    for (int dj = 0; dj < 8; dj++)
#pragma unroll
        for (int c = 0; c < 4; c++) o_acc[dj][c] = 0.f;

    int qrow = warp * 16;

    for (int kt = 0; kt < 16; kt++) {
        __syncthreads();
#pragma unroll
        for (int i = 0; i < 4; i++) {
            int idx = tid + i * 256;
            int row = idx >> 4, c4 = (idx & 15) * 4;
            const float4 kv = *(const float4*)(kb + (size_t)(kt * 64 + row) * CDIM + c4);
            const float4 vv = *(const float4*)(vb + (size_t)(kt * 64 + row) * CDIM + c4);
            *(float4*)&Ks[row * QSTR + c4] = kv;
            *(float4*)&Vs[row * VSTR + c4] = vv;
        }
        __syncthreads();

        float sv[8][4];
#pragma unroll
        for (int nj = 0; nj < 8; nj++)
#pragma unroll
            for (int c = 0; c < 4; c++) sv[nj][c] = 0.f;

#pragma unroll
        for (int ks = 0; ks < 8; ks++) {
            int r0 = (qrow + g) * QSTR, r1 = r0 + 8 * QSTR;
            unsigned a0 = __float_as_uint(Qs[r0 + ks * 8 + t]);
            unsigned a1 = __float_as_uint(Qs[r1 + ks * 8 + t]);
            unsigned a2 = __float_as_uint(Qs[r0 + ks * 8 + t + 4]);
            unsigned a3 = __float_as_uint(Qs[r1 + ks * 8 + t + 4]);
#pragma unroll
            for (int nj = 0; nj < 8; nj++) {
                unsigned b0 = __float_as_uint(Ks[(nj * 8 + g) * QSTR + ks * 8 + t]);
                unsigned b1 = __float_as_uint(Ks[(nj * 8 + g) * QSTR + ks * 8 + t + 4]);
                MMA_TF32(sv[nj], a0, a1, a2, a3, b0, b1);
            }
        }

        float m0 = -1e30f, m1 = -1e30f;
#pragma unroll
        for (int nj = 0; nj < 8; nj++) {
#pragma unroll
            for (int c = 0; c < 4; c++) sv[nj][c] *= 0.125f;
            m0 = fmaxf(m0, fmaxf(sv[nj][0], sv[nj][1]));
            m1 = fmaxf(m1, fmaxf(sv[nj][2], sv[nj][3]));
        }
        m0 = fmaxf(m0, __shfl_xor_sync(0xffffffffu, m0, 1));
        m0 = fmaxf(m0, __shfl_xor_sync(0xffffffffu, m0, 2));
        m1 = fmaxf(m1, __shfl_xor_sync(0xffffffffu, m1, 1));
        m1 = fmaxf(m1, __shfl_xor_sync(0xffffffffu, m1, 2));
        float nm0 = fmaxf(mi0, m0), nm1 = fmaxf(mi1, m1);
        float cr0 = __expf(mi0 - nm0), cr1 = __expf(mi1 - nm1);
        float s0 = 0.f, s1 = 0.f;
#pragma unroll
        for (int nj = 0; nj < 8; nj++) {
            sv[nj][0] = __expf(sv[nj][0] - nm0);
            sv[nj][1] = __expf(sv[nj][1] - nm0);
            sv[nj][2] = __expf(sv[nj][2] - nm1);
            sv[nj][3] = __expf(sv[nj][3] - nm1);
            s0 += sv[nj][0] + sv[nj][1];
            s1 += sv[nj][2] + sv[nj][3];
        }
        s0 += __shfl_xor_sync(0xffffffffu, s0, 1);
        s0 += __shfl_xor_sync(0xffffffffu, s0, 2);
        s1 += __shfl_xor_sync(0xffffffffu, s1, 1);
        s1 += __shfl_xor_sync(0xffffffffu, s1, 2);
        li0 = li0 * cr0 + s0; li1 = li1 * cr1 + s1;
        mi0 = nm0; mi1 = nm1;
#pragma unroll
        for (int dj = 0; dj < 8; dj++) {
            o_acc[dj][0] *= cr0; o_acc[dj][1] *= cr0;
            o_acc[dj][2] *= cr1; o_acc[dj][3] *= cr1;
        }

        int pr0 = (qrow + g) * QSTR, pr1 = pr0 + 8 * QSTR;
#pragma unroll
        for (int nj = 0; nj < 8; nj++) {
            *(float2*)&Ps[pr0 + nj * 8 + 2 * t] = make_float2(sv[nj][0], sv[nj][1]);
            *(float2*)&Ps[pr1 + nj * 8 + 2 * t] = make_float2(sv[nj][2], sv[nj][3]);
        }
        __syncwarp();

#pragma unroll
        for (int ks = 0; ks < 8; ks++) {
            unsigned a0 = __float_as_uint(Ps[pr0 + ks * 8 + t]);
            unsigned a1 = __float_as_uint(Ps[pr1 + ks * 8 + t]);
            unsigned a2 = __float_as_uint(Ps[pr0 + ks * 8 + t + 4]);
            unsigned a3 = __float_as_uint(Ps[pr1 + ks * 8 + t + 4]);
#pragma unroll
            for (int dj = 0; dj < 8; dj++) {
                unsigned b0 = __float_as_uint(Vs[(ks * 8 + t) * VSTR + dj * 8 + g]);
                unsigned b1 = __float_as_uint(Vs[(ks * 8 + t + 4) * VSTR + dj * 8 + g]);
                MMA_TF32(o_acc[dj], a0, a1, a2, a3, b0, b1);
            }
        }
    }

    float inv0 = 1.f / li0, inv1 = 1.f / li1;
    int gr0 = qt * 128 + qrow + g;
    __nv_bfloat16* or0 = o + ((size_t)b * S_TOK + gr0) * CDIM + head * 64;
    __nv_bfloat16* or1 = or0 + 8 * CDIM;
#pragma unroll
    for (int dj = 0; dj < 8; dj++) {
        __nv_bfloat162 p0 = make_bfloat162(__float2bfloat16(o_acc[dj][0] * inv0),
                                           __float2bfloat16(o_acc[dj][1] * inv0));
        __nv_bfloat162 p1 = make_bfloat162(__float2bfloat16(o_acc[dj][2] * inv1),
                                           __float2bfloat16(o_acc[dj][3] * inv1));
        *(unsigned*)(or0 + dj * 8 + 2 * t) = *(unsigned*)&p0;
        *(unsigned*)(or1 + dj * 8 + 2 * t) = *(unsigned*)&p1;
    }
}

// ============================================================
// launch
// ============================================================
extern "C" void kernel_launch(void* const* d_in, const int* in_sizes, int n_in,
                              void* d_out, int out_size) {
    const float* x       = (const float*)d_in[0];
    const float* gamma   = (const float*)d_in[1];
    const float* beta    = (const float*)d_in[2];
    const float* wq      = (const float*)d_in[3];
    const float* wk      = (const float*)d_in[4];
    const float* wv      = (const float*)d_in[5];
    const float* conv_w  = (const float*)d_in[6];
    const float* conv_b  = (const float*)d_in[7];
    float* out = (float*)d_out;

    __nv_bfloat16 *xnh, *abh, *wt;
    float *qb, *kb, *vb;
    cudaGetSymbolAddress((void**)&xnh, g_xn_h);
    cudaGetSymbolAddress((void**)&abh, g_attn_h);
    cudaGetSymbolAddress((void**)&wt,  g_wt);
    cudaGetSymbolAddress((void**)&qb, g_q);
    cudaGetSymbolAddress((void**)&kb, g_k);
    cudaGetSymbolAddress((void**)&vb, g_v);

    const int gemm_smem = 3 * STG_BYTES;
    const int attn_smem = (128 * QSTR + 64 * QSTR + 64 * VSTR + 128 * QSTR) * (int)sizeof(float);
    cudaFuncSetAttribute(gemm_bf16, cudaFuncAttributeMaxDynamicSharedMemorySize, gemm_smem);
    cudaFuncSetAttribute(attn_kernel, cudaFuncAttributeMaxDynamicSharedMemorySize, attn_smem);

    // GroupNorm (bf16 out) + weight transpose/convert
    gn_kernel<<<512, 256>>>(x, gamma, beta, xnh);
    wt_kernel<<<dim3(16, 16, 12), dim3(32, 8)>>>(wq, wk, wv, conv_w, wt);

    // QKV projections (bf16 tensor cores)
    dim3 ggrid(CDIM / 128, NTOK / 128);
    gemm_bf16<<<ggrid, 256, gemm_smem>>>(xnh, wt + 0 * CDIM * CDIM, qb, 1, nullptr, nullptr, 0);
    gemm_bf16<<<ggrid, 256, gemm_smem>>>(xnh, wt + 1 * CDIM * CDIM, kb, 1, nullptr, nullptr, 0);
    gemm_bf16<<<ggrid, 256, gemm_smem>>>(xnh, wt + 2 * CDIM * CDIM, vb, 1, nullptr, nullptr, 0);

    // Attention (tf32 tensor cores, bf16 out)
    attn_kernel<<<dim3(8, 8, 16), 256, attn_smem>>>(qb, kb, vb, abh);

    // 3x3 conv: fused 9-tap bf16 GEMM with bias + residual epilogue
    gemm_bf16<<<ggrid, 256, gemm_smem>>>(abh, wt + 3 * CDIM * CDIM, out, 9, conv_b, x, 1);
}

// round 7
// speedup vs baseline: 7.6561x; 1.2755x over previous
#include <cuda_runtime.h>
#include <cuda_bf16.h>
#include <stdint.h>
#include <math.h>

#define S_TOK 1024
#define CDIM  512
#define NTOK  16384   // B * S_TOK

// ---- scratch (static device globals; no runtime allocation) ----
__device__ __nv_bfloat16 g_xn_h  [NTOK * CDIM];
__device__ __nv_bfloat16 g_attn_h[NTOK * CDIM];
__device__ __nv_bfloat16 g_wt    [12 * CDIM * CDIM];  // [z][n][k] bf16
__device__ __nv_bfloat16 g_qh[NTOK * CDIM];
__device__ __nv_bfloat16 g_kh[NTOK * CDIM];
__device__ __nv_bfloat16 g_vh[NTOK * CDIM];

// ============================================================
// GroupNorm -> bf16 output
// ============================================================
__global__ void gn_kernel(const float* __restrict__ x,
                          const float* __restrict__ gamma,
                          const float* __restrict__ beta,
                          __nv_bfloat16* __restrict__ xn) {
    int bg = blockIdx.x;
    int b = bg >> 5, g = bg & 31;
    const float* xb = x + (size_t)b * S_TOK * CDIM + g * 16;
    __nv_bfloat16* xo = xn + (size_t)b * S_TOK * CDIM + g * 16;

    float sum = 0.f, sumsq = 0.f;
    for (int task = threadIdx.x; task < 4096; task += 256) {
        int s = task >> 2, c4 = (task & 3) * 4;
        float4 v = *(const float4*)(xb + s * CDIM + c4);
        sum += v.x + v.y + v.z + v.w;
        sumsq += v.x * v.x + v.y * v.y + v.z * v.z + v.w * v.w;
    }
    __shared__ float red[256], red2[256];
    red[threadIdx.x] = sum; red2[threadIdx.x] = sumsq;
    __syncthreads();
    for (int off = 128; off > 0; off >>= 1) {
        if (threadIdx.x < off) {
            red[threadIdx.x]  += red[threadIdx.x + off];
            red2[threadIdx.x] += red2[threadIdx.x + off];
        }
        __syncthreads();
    }
    float mean = red[0] * (1.f / 16384.f);
    float var  = red2[0] * (1.f / 16384.f) - mean * mean;
    float inv  = rsqrtf(var + 1e-5f);

    for (int task = threadIdx.x; task < 4096; task += 256) {
        int s = task >> 2, c4 = (task & 3) * 4;
        float4 v = *(const float4*)(xb + s * CDIM + c4);
        float4 ga = *(const float4*)(gamma + g * 16 + c4);
        float4 be = *(const float4*)(beta  + g * 16 + c4);
        float o0 = (v.x - mean) * inv * ga.x + be.x;
        float o1 = (v.y - mean) * inv * ga.y + be.y;
        float o2 = (v.z - mean) * inv * ga.z + be.z;
        float o3 = (v.w - mean) * inv * ga.w + be.w;
        __nv_bfloat162 p0 = __floats2bfloat162_rn(o0, o1);
        __nv_bfloat162 p1 = __floats2bfloat162_rn(o2, o3);
        uint2 pk = make_uint2(*(unsigned*)&p0, *(unsigned*)&p1);
        *(uint2*)(xo + s * CDIM + c4) = pk;
    }
}

// ============================================================
// Weight transpose + convert: out[z][n][k] = bf16(src_z[k][n])
// ============================================================
__global__ void wt_kernel(const float* __restrict__ wq, const float* __restrict__ wk,
                          const float* __restrict__ wv, const float* __restrict__ cw,
                          __nv_bfloat16* __restrict__ out) {
    __shared__ float tile[32][33];
    int z = blockIdx.z;
    const float* src = (z == 0) ? wq : (z == 1) ? wk : (z == 2) ? wv
                       : cw + (size_t)(z - 3) * CDIM * CDIM;
    __nv_bfloat16* dst = out + (size_t)z * CDIM * CDIM;
    int k0 = blockIdx.y * 32, n0 = blockIdx.x * 32;
    int tx = threadIdx.x, ty = threadIdx.y;
#pragma unroll
    for (int i = 0; i < 32; i += 8)
        tile[ty + i][tx] = src[(size_t)(k0 + ty + i) * CDIM + n0 + tx];
    __syncthreads();
#pragma unroll
    for (int i = 0; i < 32; i += 8)
        dst[(size_t)(n0 + ty + i) * CDIM + k0 + tx] = __float2bfloat16(tile[tx][ty + i]);
}

// ============================================================
// mma / ldmatrix / cp.async helpers
// ============================================================
#define MMA_BF16(d, a, b0, b1)                                              \
    asm volatile(                                                           \
        "mma.sync.aligned.m16n8k16.row.col.f32.bf16.bf16.f32 "              \
        "{%0,%1,%2,%3}, {%4,%5,%6,%7}, {%8,%9}, {%0,%1,%2,%3};\n"           \
        : "+f"(d[0]), "+f"(d[1]), "+f"(d[2]), "+f"(d[3])                    \
        : "r"(a[0]), "r"(a[1]), "r"(a[2]), "r"(a[3]), "r"(b0), "r"(b1))

#define LDSM4(r, addr)                                                      \
    asm volatile("ldmatrix.sync.aligned.m8n8.x4.shared.b16 {%0,%1,%2,%3}, [%4];\n" \
                 : "=r"(r[0]), "=r"(r[1]), "=r"(r[2]), "=r"(r[3]) : "r"(addr))

#define LDSM4T(r, addr)                                                     \
    asm volatile("ldmatrix.sync.aligned.m8n8.x4.trans.shared.b16 {%0,%1,%2,%3}, [%4];\n" \
                 : "=r"(r[0]), "=r"(r[1]), "=r"(r[2]), "=r"(r[3]) : "r"(addr))

#define CP_ASYNC16(daddr, gptr, sz)                                         \
    asm volatile("cp.async.cg.shared.global [%0], [%1], 16, %2;\n"          \
                 :: "r"(daddr), "l"(gptr), "r"(sz))
#define CP_COMMIT() asm volatile("cp.async.commit_group;\n")

__device__ __forceinline__ unsigned pack_bf2(float a, float b) {
    __nv_bfloat162 h = __floats2bfloat162_rn(a, b);
    return *(unsigned*)&h;
}

// ============================================================
// BF16 GEMM: C[16384,512] = sum_tap Ashift[16384,512] @ Wt_tap^T
// 128x128 tile, BK=32, 3-stage cp.async ring, 8 warps (64x32),
// ldmatrix.x4 frags, smem row stride 80B. Loads issued BEFORE
// compute each iter (stage free after barrier).
// out: bf16 (obf=1) or fp32 with bias+residual (epi=1).
// ============================================================
#define STG_BYTES 20480   // per stage: A 128*80 + B 128*80

__global__ __launch_bounds__(256)
void gemm_bf16(const __nv_bfloat16* __restrict__ A,
               const __nv_bfloat16* __restrict__ Wt,
               void* __restrict__ Cout, int ntaps, int obf,
               const float* __restrict__ bias,
               const float* __restrict__ residual, int epi) {
    extern __shared__ char smem[];

    int tid = threadIdx.x, warp = tid >> 5, lane = tid & 31;
    int g = lane >> 2, t = lane & 3;
    int m0 = blockIdx.y * 128, n0 = blockIdx.x * 128;
    int wm = (warp >> 2) * 64, wn = (warp & 3) * 32;

    int lrow = tid >> 2, lchunk = tid & 3;
    int bidx[2], hh0[2], ww0[2];
#pragma unroll
    for (int p = 0; p < 2; p++) {
        int mg = m0 + lrow + 64 * p;
        bidx[p] = mg >> 10;
        int s = mg & 1023;
        hh0[p] = s >> 5; ww0[p] = s & 31;
    }

    float acc[4][4][4];
#pragma unroll
    for (int mi = 0; mi < 4; mi++)
#pragma unroll
        for (int nj = 0; nj < 4; nj++)
#pragma unroll
            for (int c = 0; c < 4; c++) acc[mi][nj][c] = 0.f;

    const int NIT = ntaps * 16;

#define LOAD_TILE(IT, ST)                                                   \
    {                                                                       \
        int tap = (IT) >> 4;                                                \
        int k0 = ((IT) & 15) << 5;                                          \
        int dh = 0, dw = 0;                                                 \
        if (ntaps > 1) { int r3 = tap / 3; dh = r3 - 1; dw = tap - r3 * 3 - 1; } \
        char* as = smem + (ST) * STG_BYTES;                                 \
        char* bs = as + 10240;                                              \
        _Pragma("unroll")                                                   \
        for (int p = 0; p < 2; p++) {                                       \
            int hh = hh0[p] + dh, ww = ww0[p] + dw;                         \
            bool valid = ((unsigned)hh < 32u) && ((unsigned)ww < 32u);      \
            const __nv_bfloat16* gp = A + (size_t)((bidx[p] << 10) + (hh << 5) + ww) * CDIM + k0 + lchunk * 8; \
            unsigned da = (unsigned)__cvta_generic_to_shared(as + (lrow + 64 * p) * 80 + lchunk * 16); \
            CP_ASYNC16(da, gp, valid ? 16 : 0);                             \
        }                                                                   \
        const __nv_bfloat16* wb = Wt + (size_t)tap * CDIM * CDIM + (size_t)n0 * CDIM + k0; \
        _Pragma("unroll")                                                   \
        for (int p = 0; p < 2; p++) {                                       \
            const __nv_bfloat16* gp = wb + (size_t)(lrow + 64 * p) * CDIM + lchunk * 8; \
            unsigned da = (unsigned)__cvta_generic_to_shared(bs + (lrow + 64 * p) * 80 + lchunk * 16); \
            CP_ASYNC16(da, gp, 16);                                         \
        }                                                                   \
        CP_COMMIT();                                                        \
    }

    LOAD_TILE(0, 0);
    LOAD_TILE(1, 1);

    int arow_f = wm + (lane & 15);
    int akoff  = (lane >> 4) * 8;
    int brow_f = wn + (lane & 7) + ((lane >> 4) << 3);
    int bkoff  = ((lane >> 3) & 1) * 8;

    int st = 0;
    for (int it = 0; it < NIT; it++) {
        if (it + 1 < NIT) asm volatile("cp.async.wait_group 1;");
        else              asm volatile("cp.async.wait_group 0;");
        __syncthreads();
        // stage (it+2)%3 was last read at it-1; free after this barrier.
        if (it + 2 < NIT) {
            int wst = st + 2; if (wst >= 3) wst -= 3;
            LOAD_TILE(it + 2, wst);
        }
        char* as = smem + st * STG_BYTES;
        char* bs = as + 10240;
        unsigned abase = (unsigned)__cvta_generic_to_shared(as);
        unsigned bbase = (unsigned)__cvta_generic_to_shared(bs);

#pragma unroll
        for (int ks = 0; ks < 2; ks++) {
            unsigned bfr[2][4];
#pragma unroll
            for (int njp = 0; njp < 2; njp++) {
                unsigned addr = bbase + ((brow_f + njp * 16) * 40 + ks * 16 + bkoff) * 2;
                LDSM4(bfr[njp], addr);
            }
#pragma unroll
            for (int mi = 0; mi < 4; mi++) {
                unsigned af[4];
                unsigned addr = abase + ((arow_f + mi * 16) * 40 + ks * 16 + akoff) * 2;
                LDSM4(af, addr);
                MMA_BF16(acc[mi][0], af, bfr[0][0], bfr[0][1]);
                MMA_BF16(acc[mi][1], af, bfr[0][2], bfr[0][3]);
                MMA_BF16(acc[mi][2], af, bfr[1][0], bfr[1][1]);
                MMA_BF16(acc[mi][3], af, bfr[1][2], bfr[1][3]);
            }
        }
        st++; if (st == 3) st = 0;
    }

    // epilogue
#pragma unroll
    for (int mi = 0; mi < 4; mi++) {
        int r0 = m0 + wm + mi * 16 + g;
        int r1 = r0 + 8;
#pragma unroll
        for (int nj = 0; nj < 4; nj++) {
            int col = n0 + wn + nj * 8 + 2 * t;
            float2 v01 = make_float2(acc[mi][nj][0], acc[mi][nj][1]);
            float2 v23 = make_float2(acc[mi][nj][2], acc[mi][nj][3]);
            if (obf) {
                __nv_bfloat16* C = (__nv_bfloat16*)Cout;
                *(unsigned*)(C + (size_t)r0 * CDIM + col) = pack_bf2(v01.x, v01.y);
                *(unsigned*)(C + (size_t)r1 * CDIM + col) = pack_bf2(v23.x, v23.y);
            } else {
                float* C = (float*)Cout;
                if (epi) {
                    float b0v = bias[col], b1v = bias[col + 1];
                    const float* rr0 = residual + (size_t)r0 * CDIM + col;
                    const float* rr1 = residual + (size_t)r1 * CDIM + col;
                    v01.x += b0v + rr0[0]; v01.y += b1v + rr0[1];
                    v23.x += b0v + rr1[0]; v23.y += b1v + rr1[1];
                }
                *(float2*)(C + (size_t)r0 * CDIM + col) = v01;
                *(float2*)(C + (size_t)r1 * CDIM + col) = v23;
            }
        }
    }
}

// ============================================================
// BF16 tensor-core flash attention.
// Block: 128 q rows x one (b, head). 8 warps, each 16 q rows.
// Q frags hoisted to registers (loop-invariant). K via gemm-style
// B LDSM; V via ldmatrix.x4.trans; P converts reg->reg to A frags.
// Tile layout: subtiles of 32 d, row stride 80B (conflict-free).
// Smem: Q 20480 + K 10240 + V 10240 = 40960 B.
// ============================================================
__global__ __launch_bounds__(256)
void attn_bf16(const __nv_bfloat16* __restrict__ q,
               const __nv_bfloat16* __restrict__ k,
               const __nv_bfloat16* __restrict__ v,
               __nv_bfloat16* __restrict__ o) {
    extern __shared__ char sm[];
    char* Qs = sm;              // [2 subtiles][128 rows][80B]
    char* Ks = sm + 20480;      // [2][64][80]
    char* Vs = sm + 30720;      // [2][64][80]

    int qt = blockIdx.x, head = blockIdx.y, b = blockIdx.z;
    int tid = threadIdx.x, warp = tid >> 5, lane = tid & 31;
    int g = lane >> 2, t = lane & 3;

    size_t base = ((size_t)b * S_TOK) * CDIM + head * 64;
    const __nv_bfloat16* qg = q + base;
    const __nv_bfloat16* kg = k + base;
    const __nv_bfloat16* vg = v + base;

    // load Q tile [128 x 64]: 1024 16B-chunks
#pragma unroll
    for (int i = 0; i < 4; i++) {
        int idx = tid + i * 256;
        int row = idx >> 3, c = idx & 7;
        uint4 val = *(const uint4*)(qg + (size_t)(qt * 128 + row) * CDIM + c * 8);
        *(uint4*)(Qs + (c >> 2) * 10240 + row * 80 + (c & 3) * 16) = val;
    }
    __syncthreads();

    // hoist Q fragments (4 k16 steps)
    unsigned qf[4][4];
    {
        unsigned qbase = (unsigned)__cvta_generic_to_shared(Qs);
        int arow_f = warp * 16 + (lane & 15);
        int akoff = (lane >> 4) * 8;
#pragma unroll
        for (int kst = 0; kst < 4; kst++) {
            unsigned addr = qbase + (kst >> 1) * 10240 +
                            (arow_f * 40 + (kst & 1) * 16 + akoff) * 2;
            LDSM4(qf[kst], addr);
        }
    }

    float o_acc[8][4];
    float mi0 = -1e30f, mi1 = -1e30f, li0 = 0.f, li1 = 0.f;
#pragma unroll
    for (int dj = 0; dj < 8; dj++)
#pragma unroll
        for (int c = 0; c < 4; c++) o_acc[dj][c] = 0.f;

    unsigned kbase = (unsigned)__cvta_generic_to_shared(Ks);
    unsigned vbase = (unsigned)__cvta_generic_to_shared(Vs);
    int brow_f = (lane & 7) + ((lane >> 4) << 3);
    int bkoff  = ((lane >> 3) & 1) * 8;
    int vrow   = (lane & 7) + 8 * ((lane >> 3) & 1);
    int vdo    = (lane >> 4) * 8;

    for (int kt = 0; kt < 16; kt++) {
        __syncthreads();
        // load K,V tiles [64 x 64]: 512 chunks each
#pragma unroll
        for (int i = 0; i < 2; i++) {
            int idx = tid + i * 256;
            int row = idx >> 3, c = idx & 7;
            uint4 kv = *(const uint4*)(kg + (size_t)(kt * 64 + row) * CDIM + c * 8);
            uint4 vv = *(const uint4*)(vg + (size_t)(kt * 64 + row) * CDIM + c * 8);
            int off = (c >> 2) * 5120 + row * 80 + (c & 3) * 16;
            *(uint4*)(Ks + off) = kv;
            *(uint4*)(Vs + off) = vv;
        }
        __syncthreads();

        // S = Q K^T : warp [16 x 64], fp32 accum
        float sv[8][4];
#pragma unroll
        for (int nj = 0; nj < 8; nj++)
#pragma unroll
            for (int c = 0; c < 4; c++) sv[nj][c] = 0.f;

#pragma unroll
        for (int kst = 0; kst < 4; kst++) {
            unsigned kb = kbase + (kst >> 1) * 5120;
#pragma unroll
            for (int njp = 0; njp < 4; njp++) {
                unsigned bfr[4];
                unsigned addr = kb + ((brow_f + njp * 16) * 40 +
                                      (kst & 1) * 16 + bkoff) * 2;
                LDSM4(bfr, addr);
                MMA_BF16(sv[njp * 2],     qf[kst], bfr[0], bfr[1]);
                MMA_BF16(sv[njp * 2 + 1], qf[kst], bfr[2], bfr[3]);
            }
        }

        // online softmax (rows g, g+8)
        float m0 = -1e30f, m1 = -1e30f;
#pragma unroll
        for (int nj = 0; nj < 8; nj++) {
#pragma unroll
            for (int c = 0; c < 4; c++) sv[nj][c] *= 0.125f;
            m0 = fmaxf(m0, fmaxf(sv[nj][0], sv[nj][1]));
            m1 = fmaxf(m1, fmaxf(sv[nj][2], sv[nj][3]));
        }
        m0 = fmaxf(m0, __shfl_xor_sync(0xffffffffu, m0, 1));
        m0 = fmaxf(m0, __shfl_xor_sync(0xffffffffu, m0, 2));
        m1 = fmaxf(m1, __shfl_xor_sync(0xffffffffu, m1, 1));
        m1 = fmaxf(m1, __shfl_xor_sync(0xffffffffu, m1, 2));
        float nm0 = fmaxf(mi0, m0), nm1 = fmaxf(mi1, m1);
        float cr0 = __expf(mi0 - nm0), cr1 = __expf(mi1 - nm1);
        float s0 = 0.f, s1 = 0.f;
#pragma unroll
        for (int nj = 0; nj < 8; nj++) {
            sv[nj][0] = __expf(sv[nj][0] - nm0);
            sv[nj][1] = __expf(sv[nj][1] - nm0);
            sv[nj][2] = __expf(sv[nj][2] - nm1);
            sv[nj][3] = __expf(sv[nj][3] - nm1);
            s0 += sv[nj][0] + sv[nj][1];
            s1 += sv[nj][2] + sv[nj][3];
        }
        s0 += __shfl_xor_sync(0xffffffffu, s0, 1);
        s0 += __shfl_xor_sync(0xffffffffu, s0, 2);
        s1 += __shfl_xor_sync(0xffffffffu, s1, 1);
        s1 += __shfl_xor_sync(0xffffffffu, s1, 2);
        li0 = li0 * cr0 + s0; li1 = li1 * cr1 + s1;
        mi0 = nm0; mi1 = nm1;
#pragma unroll
        for (int dj = 0; dj < 8; dj++) {
            o_acc[dj][0] *= cr0; o_acc[dj][1] *= cr0;
            o_acc[dj][2] *= cr1; o_acc[dj][3] *= cr1;
        }

        // P: register C-frag -> A-frag (no smem round trip)
        unsigned pf[4][4];
#pragma unroll
        for (int j = 0; j < 4; j++) {
            pf[j][0] = pack_bf2(sv[2 * j][0],     sv[2 * j][1]);
            pf[j][1] = pack_bf2(sv[2 * j][2],     sv[2 * j][3]);
            pf[j][2] = pack_bf2(sv[2 * j + 1][0], sv[2 * j + 1][1]);
            pf[j][3] = pack_bf2(sv[2 * j + 1][2], sv[2 * j + 1][3]);
        }

        // O += P V  (V via ldmatrix.trans)
#pragma unroll
        for (int j = 0; j < 4; j++) {           // kv k16 step
#pragma unroll
            for (int djp = 0; djp < 4; djp++) { // d block pair (16 d)
                unsigned bfr[4];
                int d0 = djp * 16;
                unsigned addr = vbase + (d0 >> 5) * 5120 +
                                ((j * 16 + vrow) * 40 + (d0 & 31) + vdo) * 2;
                LDSM4T(bfr, addr);
                MMA_BF16(o_acc[djp * 2],     pf[j], bfr[0], bfr[1]);
                MMA_BF16(o_acc[djp * 2 + 1], pf[j], bfr[2], bfr[3]);
            }
        }
    }

    // normalize + write bf16, rows g / g+8
    float inv0 = 1.f / li0, inv1 = 1.f / li1;
    int gr0 = qt * 128 + warp * 16 + g;
    __nv_bfloat16* or0 = o + ((size_t)b * S_TOK + gr0) * CDIM + head * 64;
    __nv_bfloat16* or1 = or0 + 8 * CDIM;
#pragma unroll
    for (int dj = 0; dj < 8; dj++) {
        *(unsigned*)(or0 + dj * 8 + 2 * t) =
            pack_bf2(o_acc[dj][0] * inv0, o_acc[dj][1] * inv0);
        *(unsigned*)(or1 + dj * 8 + 2 * t) =
            pack_bf2(o_acc[dj][2] * inv1, o_acc[dj][3] * inv1);
    }
}

// ============================================================
// launch
// ============================================================
extern "C" void kernel_launch(void* const* d_in, const int* in_sizes, int n_in,
                              void* d_out, int out_size) {
    const float* x       = (const float*)d_in[0];
    const float* gamma   = (const float*)d_in[1];
    const float* beta    = (const float*)d_in[2];
    const float* wq      = (const float*)d_in[3];
    const float* wk      = (const float*)d_in[4];
    const float* wv      = (const float*)d_in[5];
    const float* conv_w  = (const float*)d_in[6];
    const float* conv_b  = (const float*)d_in[7];
    float* out = (float*)d_out;

    __nv_bfloat16 *xnh, *abh, *wt, *qh, *kh, *vh;
    cudaGetSymbolAddress((void**)&xnh, g_xn_h);
    cudaGetSymbolAddress((void**)&abh, g_attn_h);
    cudaGetSymbolAddress((void**)&wt,  g_wt);
    cudaGetSymbolAddress((void**)&qh, g_qh);
    cudaGetSymbolAddress((void**)&kh, g_kh);
    cudaGetSymbolAddress((void**)&vh, g_vh);

    const int gemm_smem = 3 * STG_BYTES;
    const int attn_smem = 40960;
    cudaFuncSetAttribute(gemm_bf16, cudaFuncAttributeMaxDynamicSharedMemorySize, gemm_smem);
    cudaFuncSetAttribute(attn_bf16, cudaFuncAttributeMaxDynamicSharedMemorySize, attn_smem);

    // GroupNorm (bf16 out) + weight transpose/convert
    gn_kernel<<<512, 256>>>(x, gamma, beta, xnh);
    wt_kernel<<<dim3(16, 16, 12), dim3(32, 8)>>>(wq, wk, wv, conv_w, wt);

    // QKV projections (bf16 in/out)
    dim3 ggrid(CDIM / 128, NTOK / 128);
    gemm_bf16<<<ggrid, 256, gemm_smem>>>(xnh, wt + 0 * (size_t)CDIM * CDIM, qh, 1, 1, nullptr, nullptr, 0);
    gemm_bf16<<<ggrid, 256, gemm_smem>>>(xnh, wt + 1 * (size_t)CDIM * CDIM, kh, 1, 1, nullptr, nullptr, 0);
    gemm_bf16<<<ggrid, 256, gemm_smem>>>(xnh, wt + 2 * (size_t)CDIM * CDIM, vh, 1, 1, nullptr, nullptr, 0);

    // Attention (bf16 tensor cores)
    attn_bf16<<<dim3(8, 8, 16), 256, attn_smem>>>(qh, kh, vh, abh);

    // 3x3 conv: fused 9-tap bf16 GEMM, fp32 out with bias + residual
    gemm_bf16<<<ggrid, 256, gemm_smem>>>(abh, wt + 3 * (size_t)CDIM * CDIM, out, 9, 0, conv_b, x, 1);
}